// round 10
// baseline (speedup 1.0000x reference)
#include <cuda_runtime.h>
#include <cuda_bf16.h>
#include <cstdint>

#define D_IN   64
#define D_OUT  64
#define D_HID  128
#define MAX_NODES 100000
#define NPB    128                 // nodes per tile (M tile)
#define NT     256                 // threads per block (8 warps x 16 rows)
#define PREP_SPLIT 8               // blocks computing W12

// Scratch. g_deg: consume-reset invariant (zero at load; epilogue atomicExch).
__device__ int   g_deg[MAX_NODES];
__device__ float g_bW[D_OUT];
__device__ __align__(16) unsigned short g_WT_h[D_OUT * D_IN];  // [c][k]
__device__ __align__(16) unsigned short g_WT_l[D_OUT * D_IN];
// Cross-block flags (self-resetting each call)
__device__ int g_prep;             // == PREP_SPLIT when W12 ready
__device__ int g_hist;             // == gridDim.x when histogram done
__device__ int g_exit;             // exit ticket; last block resets all

// ---------------------------------------------------------------------------
__device__ __forceinline__ void mma_bf16(float& d0, float& d1, float& d2, float& d3,
                                         uint32_t a0, uint32_t a1, uint32_t a2, uint32_t a3,
                                         uint32_t b0, uint32_t b1) {
    asm volatile(
        "mma.sync.aligned.m16n8k16.row.col.f32.bf16.bf16.f32 "
        "{%0,%1,%2,%3}, {%4,%5,%6,%7}, {%8,%9}, {%0,%1,%2,%3};"
        : "+f"(d0), "+f"(d1), "+f"(d2), "+f"(d3)
        : "r"(a0), "r"(a1), "r"(a2), "r"(a3), "r"(b0), "r"(b1));
}

// ---------------------------------------------------------------------------
// SMEM byte offsets (dynamic)
#define SM_SC  0                              // 128 f32 scales (1+deg)
#define SM_BW  512                            // 64 f32
#define SM_B2  768                            // 64 f32
#define SM_WH  1024                           // 64 x 144B
#define SM_WL  (SM_WH + 64 * 144)             // 64 x 144B
#define SM_XH  (SM_WL + 64 * 144)             // 128 x 144B
#define SM_XL  (SM_XH + 128 * 144)            // 128 x 144B
#define SM_TOTAL (SM_XL + 128 * 144)          // 56320 B

// ---------------------------------------------------------------------------
// Fused persistent kernel: prep (blocks 0..7) + degree hist (all blocks) +
// tiled HMMA GEMM with (1+deg) epilogue. All blocks resident by construction.
__global__ __launch_bounds__(NT, 3) void gnn_fused_kernel(
    const float* __restrict__ x,
    const int*   __restrict__ ei32,
    const float* __restrict__ W1,
    const float* __restrict__ b1,
    const float* __restrict__ W2,
    const float* __restrict__ b2,
    float* __restrict__ out,
    int n, int E)
{
    extern __shared__ char smem[];
    const int tid = threadIdx.x;
    const int wid = tid >> 5;
    const int lid = tid & 31;
    const int g   = lid >> 2;                  // 0..7
    const int t   = lid & 3;                   // 0..3
    const int bid = blockIdx.x;
    const int grid = gridDim.x;

    // ---- Phase P: W12 prep on blocks [0, PREP_SPLIT) ----
    if (bid < PREP_SPLIT) {
        #pragma unroll
        for (int it = 0; it < 2; ++it) {
            const int o = it * NT + tid;       // 0..511
            const int r = bid * 8 + (o >> 6);  // global k-row
            const int j = o & 63;              // output col
            const float* w1r = W1 + (size_t)r * D_HID;
            float a = 0.f;
            #pragma unroll 8
            for (int k = 0; k < D_HID; ++k)
                a = fmaf(w1r[k], W2[(size_t)k * D_OUT + j], a);
            __nv_bfloat16 h = __float2bfloat16_rn(a);
            __nv_bfloat16 l = __float2bfloat16_rn(a - __bfloat162float(h));
            g_WT_h[j * D_IN + r] = *reinterpret_cast<unsigned short*>(&h);
            g_WT_l[j * D_IN + r] = *reinterpret_cast<unsigned short*>(&l);
        }
        if (bid == 0 && tid < D_OUT) {         // bW = b1 @ W2
            float a = 0.f;
            #pragma unroll 8
            for (int k = 0; k < D_HID; ++k)
                a = fmaf(b1[k], W2[(size_t)k * D_OUT + tid], a);
            g_bW[tid] = a;
        }
        __syncthreads();
        if (tid == 0) { __threadfence(); atomicAdd(&g_prep, 1); }
    }

    // ---- Phase H: degree histogram slice (dtype self-detecting) ----
    {
        __shared__ int s_is64;
        if (tid == 0) {
            int is64 = 1;
            #pragma unroll
            for (int i = 1; i < 64; i += 2)
                if (ei32[i] != 0) is64 = 0;
            s_is64 = is64;
        }
        __syncthreads();

        long long chunk = (((long long)E + grid - 1) / grid + 3) & ~3LL;
        const long long s = (long long)bid * chunk;
        const long long e = (s + chunk < (long long)E) ? s + chunk : (long long)E;

        if (s_is64) {
            const unsigned long long* p = (const unsigned long long*)ei32 + E;
            for (long long i = s + (long long)tid * 4; i < e; i += (long long)NT * 4) {
                if (i + 4 <= e) {
                    ulonglong2 a = ((const ulonglong2*)(p + i))[0];
                    ulonglong2 b = ((const ulonglong2*)(p + i))[1];
                    atomicAdd(&g_deg[(int)a.x], 1); atomicAdd(&g_deg[(int)a.y], 1);
                    atomicAdd(&g_deg[(int)b.x], 1); atomicAdd(&g_deg[(int)b.y], 1);
                } else {
                    for (long long j = i; j < e; ++j) atomicAdd(&g_deg[(int)p[j]], 1);
                }
            }
        } else {
            const int* p = (const int*)ei32 + E;
            for (long long i = s + (long long)tid * 4; i < e; i += (long long)NT * 4) {
                if (i + 4 <= e) {
                    int4 v = *(const int4*)(p + i);
                    atomicAdd(&g_deg[v.x], 1); atomicAdd(&g_deg[v.y], 1);
                    atomicAdd(&g_deg[v.z], 1); atomicAdd(&g_deg[v.w], 1);
                } else {
                    for (long long j = i; j < e; ++j) atomicAdd(&g_deg[p[j]], 1);
                }
            }
        }
        __syncthreads();
        if (tid == 0) { __threadfence(); atomicAdd(&g_hist, 1); }
    }

    // ---- Wait for W12, then stage it (+biases) once ----
    if (tid == 0) {
        while (*(volatile int*)&g_prep < PREP_SPLIT) {}
        __threadfence();
    }
    __syncthreads();

    if (tid < D_OUT) {
        ((float*)(smem + SM_BW))[tid] = g_bW[tid];
        ((float*)(smem + SM_B2))[tid] = b2[tid];
    }
    #pragma unroll
    for (int it = 0; it < 4; ++it) {
        const int u = it * NT + tid;           // 0..1023
        const int c = u >> 4, q = u & 15;
        *(uint2*)(smem + SM_WH + c * 144 + q * 8) =
            *(const uint2*)((const char*)g_WT_h + c * 128 + q * 8);
        *(uint2*)(smem + SM_WL + c * 144 + q * 8) =
            *(const uint2*)((const char*)g_WT_l + c * 128 + q * 8);
    }

    // ---- Phase G: GEMM tiles striped over blocks ----
    const int nTiles = (n + NPB - 1) / NPB;
    bool histSeen = false;

    for (int tile = bid; tile < nTiles; tile += grid) {
        const int base = tile * NPB;

        // Stage x: f32 -> bf16 hi/lo, padded rows
        #pragma unroll
        for (int it = 0; it < 8; ++it) {
            const int u = it * NT + tid;       // 0..2047
            const int row = u >> 4, q4 = u & 15;
            const int gr = (base + row < n) ? (base + row) : (n - 1);
            const float4 v = ((const float4*)(x + (size_t)gr * D_IN))[q4];

            __nv_bfloat16 h0 = __float2bfloat16_rn(v.x);
            __nv_bfloat16 h1 = __float2bfloat16_rn(v.y);
            __nv_bfloat16 h2 = __float2bfloat16_rn(v.z);
            __nv_bfloat16 h3 = __float2bfloat16_rn(v.w);
            __nv_bfloat16 l0 = __float2bfloat16_rn(v.x - __bfloat162float(h0));
            __nv_bfloat16 l1 = __float2bfloat16_rn(v.y - __bfloat162float(h1));
            __nv_bfloat16 l2 = __float2bfloat16_rn(v.z - __bfloat162float(h2));
            __nv_bfloat16 l3 = __float2bfloat16_rn(v.w - __bfloat162float(h3));

            uint2 hv, lv;
            __nv_bfloat162 p;
            p = __halves2bfloat162(h0, h1); hv.x = *reinterpret_cast<uint32_t*>(&p);
            p = __halves2bfloat162(h2, h3); hv.y = *reinterpret_cast<uint32_t*>(&p);
            p = __halves2bfloat162(l0, l1); lv.x = *reinterpret_cast<uint32_t*>(&p);
            p = __halves2bfloat162(l2, l3); lv.y = *reinterpret_cast<uint32_t*>(&p);

            *(uint2*)(smem + SM_XH + row * 144 + q4 * 8) = hv;
            *(uint2*)(smem + SM_XL + row * 144 + q4 * 8) = lv;
        }
        __syncthreads();

        // HMMA mainloop: warp owns rows [16*wid, 16*wid+16)
        float acc[32];
        #pragma unroll
        for (int i = 0; i < 32; ++i) acc[i] = 0.f;

        const int rowA = wid * 16 + g;
        const uint32_t aoff = (uint32_t)(rowA * 144 + 4 * t);
        const uint32_t boff = (uint32_t)(g * 144 + 4 * t);

        #pragma unroll
        for (int ks = 0; ks < 4; ++ks) {
            const uint32_t ak = aoff + ks * 32;
            const uint32_t ah0 = *(const uint32_t*)(smem + SM_XH + ak);
            const uint32_t ah1 = *(const uint32_t*)(smem + SM_XH + ak + 8 * 144);
            const uint32_t ah2 = *(const uint32_t*)(smem + SM_XH + ak + 16);
            const uint32_t ah3 = *(const uint32_t*)(smem + SM_XH + ak + 8 * 144 + 16);
            const uint32_t al0 = *(const uint32_t*)(smem + SM_XL + ak);
            const uint32_t al1 = *(const uint32_t*)(smem + SM_XL + ak + 8 * 144);
            const uint32_t al2 = *(const uint32_t*)(smem + SM_XL + ak + 16);
            const uint32_t al3 = *(const uint32_t*)(smem + SM_XL + ak + 8 * 144 + 16);

            #pragma unroll
            for (int nt = 0; nt < 8; ++nt) {
                const uint32_t bk = boff + nt * 8 * 144 + ks * 32;
                const uint32_t bh0 = *(const uint32_t*)(smem + SM_WH + bk);
                const uint32_t bh1 = *(const uint32_t*)(smem + SM_WH + bk + 16);
                const uint32_t bl0 = *(const uint32_t*)(smem + SM_WL + bk);
                const uint32_t bl1 = *(const uint32_t*)(smem + SM_WL + bk + 16);
                float* a = acc + nt * 4;
                mma_bf16(a[0], a[1], a[2], a[3], ah0, ah1, ah2, ah3, bh0, bh1);
                mma_bf16(a[0], a[1], a[2], a[3], ah0, ah1, ah2, ah3, bl0, bl1);
                mma_bf16(a[0], a[1], a[2], a[3], al0, al1, al2, al3, bh0, bh1);
            }
        }

        // Wait for histogram completion (once), then fetch degrees (L2-coherent)
        if (!histSeen) {
            if (tid == 0) {
                while (*(volatile int*)&g_hist < grid) {}
            }
            histSeen = true;
        }
        __syncthreads();
        if (tid < NPB) {
            const int node = base + tid;
            int d = 0;
            if (node < n) d = atomicExch(&g_deg[node], 0);   // read + consume-reset
            ((float*)(smem + SM_SC))[tid] = 1.0f + (float)d;
        }
        __syncthreads();

        // Direct-from-fragment epilogue
        {
            const float* sc = (const float*)(smem + SM_SC);
            const float* bw = (const float*)(smem + SM_BW);
            const float* bb = (const float*)(smem + SM_B2);
            const int r0 = wid * 16 + g;
            const int node0 = base + r0;
            const int node1 = node0 + 8;
            const bool v0 = (node0 < n);
            const bool v1 = (node1 < n);
            const float s0 = sc[r0];
            const float s1 = sc[r0 + 8];
            float* op0 = out + (size_t)node0 * D_OUT;
            float* op1 = out + (size_t)node1 * D_OUT;

            #pragma unroll
            for (int nt = 0; nt < 8; ++nt) {
                const int c = nt * 8 + 2 * t;
                const float2 bwv = *(const float2*)(bw + c);
                const float2 bbv = *(const float2*)(bb + c);
                const float* a = acc + nt * 4;
                if (v0) {
                    float2 r;
                    r.x = fmaf(s0, a[0] + bwv.x, bbv.x);
                    r.y = fmaf(s0, a[1] + bwv.y, bbv.y);
                    *(float2*)(op0 + c) = r;
                }
                if (v1) {
                    float2 r;
                    r.x = fmaf(s1, a[2] + bwv.x, bbv.x);
                    r.y = fmaf(s1, a[3] + bwv.y, bbv.y);
                    *(float2*)(op1 + c) = r;
                }
            }
        }
        __syncthreads();   // smem reuse safety before next tile's staging
    }

    // ---- Exit protocol: last block resets the cross-call flags ----
    if (tid == 0) {
        __threadfence();
        if (atomicAdd(&g_exit, 1) == grid - 1) {
            g_prep = 0;
            g_hist = 0;
            g_exit = 0;
            __threadfence();
        }
    }
}

// ---------------------------------------------------------------------------
extern "C" void kernel_launch(void* const* d_in, const int* in_sizes, int n_in,
                              void* d_out, int out_size) {
    const float* x  = (const float*)d_in[0];
    const int*   ei = (const int*)d_in[1];
    const float* W1 = (const float*)d_in[2];
    const float* b1 = (const float*)d_in[3];
    const float* W2 = (const float*)d_in[4];
    const float* b2 = (const float*)d_in[5];
    float* out = (float*)d_out;

    const int n = in_sizes[0] / D_IN;   // 100000
    const int E = in_sizes[1] / 2;      // 1000000

    cudaFuncSetAttribute(gnn_fused_kernel,
                         cudaFuncAttributeMaxDynamicSharedMemorySize, SM_TOTAL);

    // Grid sized to guaranteed-resident blocks (persistent-kernel safety).
    int smCount = 148, maxB = 3;
    cudaDeviceGetAttribute(&smCount, cudaDevAttrMultiProcessorCount, 0);
    cudaOccupancyMaxActiveBlocksPerMultiprocessor(&maxB, gnn_fused_kernel,
                                                  NT, SM_TOTAL);
    if (maxB < 1) maxB = 1;
    if (maxB > 3) maxB = 3;
    const int grid = smCount * maxB;

    gnn_fused_kernel<<<grid, NT, SM_TOTAL>>>(x, ei, W1, b1, W2, b2, out, n, E);
}

// round 11
// speedup vs baseline: 1.3774x; 1.3774x over previous
#include <cuda_runtime.h>
#include <cuda_bf16.h>
#include <cstdint>

#define D_IN   64
#define D_OUT  64
#define D_HID  128
#define MAX_NODES 100000
#define NPB    128                 // nodes per block (M tile)
#define NT     256                 // threads per block (8 warps x 16 rows)
#define PREP_BLOCKS 65
#define EPT    8

// Scratch. g_deg: consume-reset invariant (zero at load, reset after read).
__device__ int   g_deg[MAX_NODES];
__device__ float g_bW[D_OUT];
// W12^T row-major [c][k], bf16 hi/lo (k contiguous).
__device__ __align__(16) unsigned short g_WT_h[D_OUT * D_IN];
__device__ __align__(16) unsigned short g_WT_l[D_OUT * D_IN];

// ---------------------------------------------------------------------------
__device__ __forceinline__ void mma_bf16(float& d0, float& d1, float& d2, float& d3,
                                         uint32_t a0, uint32_t a1, uint32_t a2, uint32_t a3,
                                         uint32_t b0, uint32_t b1) {
    asm volatile(
        "mma.sync.aligned.m16n8k16.row.col.f32.bf16.bf16.f32 "
        "{%0,%1,%2,%3}, {%4,%5,%6,%7}, {%8,%9}, {%0,%1,%2,%3};"
        : "+f"(d0), "+f"(d1), "+f"(d2), "+f"(d3)
        : "r"(a0), "r"(a1), "r"(a2), "r"(a3), "r"(b0), "r"(b1));
}

// Split a float2 into packed bf16x2 hi + lo (residual) fragments.
__device__ __forceinline__ void split2(float2 f, uint32_t& hi, uint32_t& lo) {
    __nv_bfloat162 h = __float22bfloat162_rn(f);
    float2 r;
    r.x = f.x - __bfloat162float(__low2bfloat16(h));
    r.y = f.y - __bfloat162float(__high2bfloat16(h));
    __nv_bfloat162 l = __float22bfloat162_rn(r);
    hi = *reinterpret_cast<uint32_t*>(&h);
    lo = *reinterpret_cast<uint32_t*>(&l);
}

// ---------------------------------------------------------------------------
// K1: blocks [0,65) -> W12^T hi/lo bf16 + bW. Rest: degree histogram.
__global__ __launch_bounds__(256) void prep_hist_kernel(
    const int* __restrict__ ei32,
    const float* __restrict__ W1,
    const float* __restrict__ b1,
    const float* __restrict__ W2,
    int E)
{
    const int tid = threadIdx.x;

    if (blockIdx.x < PREP_BLOCKS) {
        const int r  = blockIdx.x;       // k index (or 64 => bW)
        const int j  = tid & 63;         // output column c
        const int kc = tid >> 6;
        const float* src = (r < D_IN) ? (W1 + (size_t)r * D_HID) : b1;

        float a = 0.f;
        #pragma unroll 8
        for (int k = kc * 32; k < kc * 32 + 32; ++k)
            a = fmaf(src[k], W2[(size_t)k * D_OUT + j], a);

        __shared__ float red[4][64];
        red[kc][j] = a;
        __syncthreads();
        if (kc == 0) {
            float v = red[0][j] + red[1][j] + red[2][j] + red[3][j];
            if (r < D_IN) {
                __nv_bfloat16 h = __float2bfloat16_rn(v);
                __nv_bfloat16 l = __float2bfloat16_rn(v - __bfloat162float(h));
                g_WT_h[j * D_IN + r] = *reinterpret_cast<unsigned short*>(&h);
                g_WT_l[j * D_IN + r] = *reinterpret_cast<unsigned short*>(&l);
            } else {
                g_bW[j] = v;
            }
        }
        return;
    }

    // ---- histogram over edge_index[1] (dst row), dtype self-detecting ----
    __shared__ int s_is64;
    if (tid == 0) {
        int is64 = 1;
        #pragma unroll
        for (int i = 1; i < 64; i += 2)
            if (ei32[i] != 0) is64 = 0;
        s_is64 = is64;
    }
    __syncthreads();

    const int hb = blockIdx.x - PREP_BLOCKS;
    const long long i0 = ((long long)hb * 256 + tid) * EPT;
    if (i0 >= E) return;

    if (s_is64) {
        const unsigned long long* p = (const unsigned long long*)ei32 + E;
        if (i0 + EPT <= E) {
            const ulonglong2* q = (const ulonglong2*)(p + i0);
            #pragma unroll
            for (int c = 0; c < EPT / 2; ++c) {
                ulonglong2 v = q[c];
                atomicAdd(&g_deg[(int)v.x], 1);
                atomicAdd(&g_deg[(int)v.y], 1);
            }
        } else {
            for (long long j = i0; j < E; ++j) atomicAdd(&g_deg[(int)p[j]], 1);
        }
    } else {
        const int* p = (const int*)ei32 + E;
        if (i0 + EPT <= E) {
            const int4* q = (const int4*)(p + i0);
            #pragma unroll
            for (int c = 0; c < EPT / 4; ++c) {
                int4 v = q[c];
                atomicAdd(&g_deg[v.x], 1); atomicAdd(&g_deg[v.y], 1);
                atomicAdd(&g_deg[v.z], 1); atomicAdd(&g_deg[v.w], 1);
            }
        } else {
            for (long long j = i0; j < E; ++j) atomicAdd(&g_deg[p[j]], 1);
        }
    }
}

// ---------------------------------------------------------------------------
// SMEM byte offsets (dynamic) — W tile + biases + scales only (no x tile).
#define SM_SC  0                              // 128 f32 scales (1+deg)
#define SM_BW  512                            // 64 f32
#define SM_B2  768                            // 64 f32
#define SM_WH  1024                           // 64 x 144B
#define SM_WL  (SM_WH + 64 * 144)             // 64 x 144B
#define SM_TOTAL (SM_WL + 64 * 144)           // 19456 B

// K2 (HMMA): per block of 128 nodes, D = xh@Wh + xh@Wl + xl@Wh (fp32 acc),
//            out[n] = (1+deg)*(D[n] + bW) + b2.
// A fragments are loaded DIRECTLY from global (each x element is consumed by
// exactly one thread — staging through smem was a pure roundtrip) and split
// to bf16 hi/lo in registers. No block barrier before the mainloop.
__global__ __launch_bounds__(NT, 3) void gnn_mma_kernel(
    const float* __restrict__ x,
    const float* __restrict__ b2,
    float* __restrict__ out,
    int n)
{
    extern __shared__ char smem[];
    const int tid = threadIdx.x;
    const int wid = tid >> 5;
    const int lid = tid & 31;
    const int g   = lid >> 2;                  // 0..7
    const int t   = lid & 3;                   // 0..3
    const int base = blockIdx.x * NPB;

    // Degree read + consume-reset + scale into smem
    if (tid < NPB) {
        const int node = base + tid;
        int d = 0;
        if (node < n) { d = g_deg[node]; g_deg[node] = 0; }
        ((float*)(smem + SM_SC))[tid] = 1.0f + (float)d;
    }
    if (tid < D_OUT) {
        ((float*)(smem + SM_BW))[tid] = g_bW[tid];
        ((float*)(smem + SM_B2))[tid] = b2[tid];
    }

    // Stage W^T hi/lo: 64 rows x 64 bf16 (=16 uint2/row) -> padded rows
    #pragma unroll
    for (int it = 0; it < 4; ++it) {
        const int u = it * NT + tid;           // 0..1023
        const int c = u >> 4, q = u & 15;
        *(uint2*)(smem + SM_WH + c * 144 + q * 8) =
            *(const uint2*)((const char*)g_WT_h + c * 128 + q * 8);
        *(uint2*)(smem + SM_WL + c * 144 + q * 8) =
            *(const uint2*)((const char*)g_WT_l + c * 128 + q * 8);
    }
    __syncthreads();

    // ---- HMMA mainloop: warp owns rows [16*wid, 16*wid+16) ----
    float acc[32];                             // 8 n-tiles x {d0,d1,d2,d3}
    #pragma unroll
    for (int i = 0; i < 32; ++i) acc[i] = 0.f;

    const int rowA = base + wid * 16 + g;      // global node for a0/a2
    const int r0c  = (rowA     < n) ? rowA     : (n - 1);
    const int r1c  = (rowA + 8 < n) ? rowA + 8 : (n - 1);
    const float* xr0 = x + (size_t)r0c * D_IN;
    const float* xr1 = x + (size_t)r1c * D_IN;
    const uint32_t boff = (uint32_t)(g * 144 + 4 * t);

    #pragma unroll
    for (int ks = 0; ks < 4; ++ks) {
        const int c0 = ks * 16 + 2 * t;
        // Direct A fragment loads (float2 each), split to bf16 hi/lo
        const float2 f00 = *(const float2*)(xr0 + c0);       // a0
        const float2 f10 = *(const float2*)(xr1 + c0);       // a1
        const float2 f01 = *(const float2*)(xr0 + c0 + 8);   // a2
        const float2 f11 = *(const float2*)(xr1 + c0 + 8);   // a3

        uint32_t ah0, al0, ah1, al1, ah2, al2, ah3, al3;
        split2(f00, ah0, al0);
        split2(f10, ah1, al1);
        split2(f01, ah2, al2);
        split2(f11, ah3, al3);

        #pragma unroll
        for (int nt = 0; nt < 8; ++nt) {
            const uint32_t bk = boff + nt * 8 * 144 + ks * 32;
            const uint32_t bh0 = *(const uint32_t*)(smem + SM_WH + bk);
            const uint32_t bh1 = *(const uint32_t*)(smem + SM_WH + bk + 16);
            const uint32_t bl0 = *(const uint32_t*)(smem + SM_WL + bk);
            const uint32_t bl1 = *(const uint32_t*)(smem + SM_WL + bk + 16);
            float* a = acc + nt * 4;
            mma_bf16(a[0], a[1], a[2], a[3], ah0, ah1, ah2, ah3, bh0, bh1);
            mma_bf16(a[0], a[1], a[2], a[3], ah0, ah1, ah2, ah3, bl0, bl1);
            mma_bf16(a[0], a[1], a[2], a[3], al0, al1, al2, al3, bh0, bh1);
        }
    }

    // ---- Direct-from-fragment epilogue ----
    {
        const float* sc = (const float*)(smem + SM_SC);
        const float* bw = (const float*)(smem + SM_BW);
        const float* bb = (const float*)(smem + SM_B2);
        const int r0 = wid * 16 + g;
        const int node0 = base + r0;
        const int node1 = node0 + 8;
        const bool v0 = (node0 < n);
        const bool v1 = (node1 < n);
        const float s0 = sc[r0];
        const float s1 = sc[r0 + 8];
        float* op0 = out + (size_t)node0 * D_OUT;
        float* op1 = out + (size_t)node1 * D_OUT;

        #pragma unroll
        for (int nt = 0; nt < 8; ++nt) {
            const int c = nt * 8 + 2 * t;
            const float2 bwv = *(const float2*)(bw + c);
            const float2 bbv = *(const float2*)(bb + c);
            const float* a = acc + nt * 4;
            if (v0) {
                float2 r;
                r.x = fmaf(s0, a[0] + bwv.x, bbv.x);
                r.y = fmaf(s0, a[1] + bwv.y, bbv.y);
                *(float2*)(op0 + c) = r;
            }
            if (v1) {
                float2 r;
                r.x = fmaf(s1, a[2] + bwv.x, bbv.x);
                r.y = fmaf(s1, a[3] + bwv.y, bbv.y);
                *(float2*)(op1 + c) = r;
            }
        }
    }
}

// ---------------------------------------------------------------------------
extern "C" void kernel_launch(void* const* d_in, const int* in_sizes, int n_in,
                              void* d_out, int out_size) {
    const float* x  = (const float*)d_in[0];
    const void*  ei = d_in[1];
    const float* W1 = (const float*)d_in[2];
    const float* b1 = (const float*)d_in[3];
    const float* W2 = (const float*)d_in[4];
    const float* b2 = (const float*)d_in[5];
    float* out = (float*)d_out;

    const int n = in_sizes[0] / D_IN;   // 100000
    const int E = in_sizes[1] / 2;      // 1000000

    const int hist_blocks = (E + 256 * EPT - 1) / (256 * EPT);
    prep_hist_kernel<<<PREP_BLOCKS + hist_blocks, 256>>>(
        (const int*)ei, W1, b1, W2, E);

    cudaFuncSetAttribute(gnn_mma_kernel,
                         cudaFuncAttributeMaxDynamicSharedMemorySize, SM_TOTAL);
    gnn_mma_kernel<<<(n + NPB - 1) / NPB, NT, SM_TOTAL>>>(x, b2, out, n);
}